// round 2
// baseline (speedup 1.0000x reference)
#include <cuda_runtime.h>

// RWKV WKV recurrence: a_t = exp(w_t)*a_{t-1} + exp(k_t)
//                      b_t = exp(w_t)*b_{t-1} + exp(k_t)*v_t
//                      out_t = b_t / a_t
// B=16, T=2048, D=1024, fp32. One thread per (b,d) channel, sequential in t.
// Double-buffered register prefetch of UU timesteps keeps 3*UU=48 LDGs in
// flight per warp to hide HBM latency at 1-warp/SMSP occupancy.

#define TT 2048
#define DD 1024
#define UU 16
#define NBLK (TT / UU)

__global__ void __launch_bounds__(128, 1)
wkv_kernel(const float* __restrict__ k,
           const float* __restrict__ v,
           const float* __restrict__ w,
           float* __restrict__ out)
{
    const int c  = blockIdx.x * blockDim.x + threadIdx.x;  // 0 .. B*D-1
    const int bi = c >> 10;          // c / DD
    const int di = c & (DD - 1);     // c % DD
    const long base = (long)bi * TT * DD + di;

    const float* kp = k + base;
    const float* vp = v + base;
    const float* wp = w + base;
    float*       op = out + base;

    float a  = 0.0f;
    float bb = 0.0f;

    float kb[2][UU], vb[2][UU], wb[2][UU];

    // Prologue: load block 0 (48 independent LDGs, front-batched)
#pragma unroll
    for (int i = 0; i < UU; i++) {
        kb[0][i] = kp[i * DD];
        vb[0][i] = vp[i * DD];
        wb[0][i] = wp[i * DD];
    }

    int cur = 0;

    for (int blk = 0; blk < NBLK - 1; blk++) {
        const int nxt = cur ^ 1;
        const float* kq = kp + (long)(blk + 1) * UU * DD;
        const float* vq = vp + (long)(blk + 1) * UU * DD;
        const float* wq = wp + (long)(blk + 1) * UU * DD;

        // Prefetch next block — independent of the compute chain below, so
        // these 48 LDGs issue before the MUFU/FMA serial section and their
        // latency overlaps it.
#pragma unroll
        for (int i = 0; i < UU; i++) {
            kb[nxt][i] = kq[i * DD];
            vb[nxt][i] = vq[i * DD];
            wb[nxt][i] = wq[i * DD];
        }

        float* o = op + (long)blk * UU * DD;
#pragma unroll
        for (int i = 0; i < UU; i++) {
            float ew = __expf(wb[cur][i]);
            float ek = __expf(kb[cur][i]);
            a  = fmaf(ew, a,  ek);
            bb = fmaf(ew, bb, ek * vb[cur][i]);
            o[i * DD] = __fdividef(bb, a);
        }
        cur = nxt;
    }

    // Epilogue: final block, no prefetch
    {
        float* o = op + (long)(NBLK - 1) * UU * DD;
#pragma unroll
        for (int i = 0; i < UU; i++) {
            float ew = __expf(wb[cur][i]);
            float ek = __expf(kb[cur][i]);
            a  = fmaf(ew, a,  ek);
            bb = fmaf(ew, bb, ek * vb[cur][i]);
            o[i * DD] = __fdividef(bb, a);
        }
    }
}

extern "C" void kernel_launch(void* const* d_in, const int* in_sizes, int n_in,
                              void* d_out, int out_size)
{
    const float* k = (const float*)d_in[0];
    const float* v = (const float*)d_in[1];
    const float* w = (const float*)d_in[2];
    float* out = (float*)d_out;

    // 16384 channels / 128 threads = 128 blocks; one block per SM on 128 of
    // 148 SMs — balanced, no SM holds 2 blocks.
    wkv_kernel<<<128, 128>>>(k, v, w, out);
}